// round 15
// baseline (speedup 1.0000x reference)
#include <cuda_runtime.h>
#include <cuda_bf16.h>
#include <cuda_fp16.h>
#include <cuda_fp8.h>
#include <cstdint>

typedef __half h16;

#define Bn   8
#define Vn   4096
#define CIN  256
#define Fn   128
#define En   256
#define NCH  16

// ---------------- scratch (device globals) -----------------------------------
__device__ float g_a   [Bn*Fn];
__device__ float g_Binv[Bn*En];
__device__ float g_p1  [Bn*NCH*Fn*En];
__device__ float g_p2  [Bn*NCH*En*CIN];
__device__ float g_xp  [Bn*NCH*CIN];
__device__ float g_cp  [Bn*NCH*En];
// fp16 operands
__device__ h16 g_x16 [Bn*Vn*CIN];
__device__ h16 g_wphi16[CIN*Fn];
__device__ h16 g_w216[CIN*En];
__device__ h16 g_phi16[Bn*Vn*Fn];
__device__ h16 g_M16 [Bn*Vn*En];
__device__ h16 g_H16 [Bn*Vn*En];
__device__ h16 g_t16 [Bn*Fn*En];
__device__ h16 g_tmp16[Bn*En*CIN];
__device__ h16 g_y16 [Bn*Vn*CIN];
// fp8 operands for the conv
__device__ uint8_t g_x8 [Bn*Vn*CIN];           // e4m3(x)
__device__ uint8_t g_w8t[49*En*CIN];           // e4m3(64*w) transposed [tap][e][c]

#define WSCALE     64.0f
#define WSCALE_INV (1.0f/64.0f)

// =================== helpers =================================================
#define N_X  (Bn*Vn*CIN)
#define N_WP (CIN*Fn)
#define N_W2 (CIN*En)
#define N_CV (N_X + N_WP + N_W2)

__global__ void cvt_all(const float* __restrict__ x,
                        const float* __restrict__ wphi, const float* __restrict__ w2,
                        h16* __restrict__ x16, uint8_t* __restrict__ x8,
                        h16* __restrict__ wphi16, h16* __restrict__ w216){
    long i = (long)blockIdx.x*256 + threadIdx.x;
    if (i < N_X){
        float v = x[i];
        x16[i] = __float2half_rn(v);
        x8[i]  = (uint8_t)__nv_cvt_float_to_fp8(v, __NV_SATFINITE, __NV_E4M3);
    } else if (i < N_X+N_WP){
        wphi16[i-N_X] = __float2half_rn(wphi[i-N_X]);
    } else if (i < N_CV){
        w216[i-N_X-N_WP] = __float2half_rn(w2[i-N_X-N_WP]);
    }
}

// tiled transpose + quantize: wm[tap][c][e] -> w8t[tap][e][c] = e4m3(64*w)
__global__ void cvt_wt8(const float* __restrict__ wm, uint8_t* __restrict__ w8t){
    __shared__ float tile[32][33];
    int bx = blockIdx.x;              // 49 taps * 64 tiles
    int tap = bx >> 6, tt = bx & 63;
    int e0 = (tt & 7) * 32, c0 = (tt >> 3) * 32;
    int tx = threadIdx.x & 31, ty = threadIdx.x >> 5;   // 32 x 8
    #pragma unroll
    for (int j = 0; j < 4; j++){
        int c = c0 + ty + 8*j;
        tile[ty + 8*j][tx] = wm[((long)tap*CIN + c)*En + e0 + tx];
    }
    __syncthreads();
    #pragma unroll
    for (int j = 0; j < 4; j++){
        int e = e0 + ty + 8*j;
        float v = tile[tx][ty + 8*j] * WSCALE;
        w8t[((long)tap*En + e)*CIN + c0 + tx] =
            (uint8_t)__nv_cvt_float_to_fp8(v, __NV_SATFINITE, __NV_E4M3);
    }
}

__device__ __forceinline__ uint32_t smem_u32(const void* p) {
    uint32_t a;
    asm("{ .reg .u64 t; cvta.to.shared.u64 t, %1; cvt.u32.u64 %0, t; }" : "=r"(a) : "l"(p));
    return a;
}
__device__ __forceinline__ void cp16(uint32_t d, const void* s, int sz){
    asm volatile("cp.async.cg.shared.global [%0], [%1], 16, %2;"
                 :: "r"(d), "l"(s), "r"(sz) : "memory");
}
__device__ __forceinline__ void ldsm4(uint32_t* r, uint32_t a){
    asm volatile("ldmatrix.sync.aligned.m8n8.x4.shared.b16 {%0,%1,%2,%3}, [%4];"
                 : "=r"(r[0]),"=r"(r[1]),"=r"(r[2]),"=r"(r[3]) : "r"(a));
}
__device__ __forceinline__ void ldsm4t(uint32_t* r, uint32_t a){
    asm volatile("ldmatrix.sync.aligned.m8n8.x4.trans.shared.b16 {%0,%1,%2,%3}, [%4];"
                 : "=r"(r[0]),"=r"(r[1]),"=r"(r[2]),"=r"(r[3]) : "r"(a));
}
__device__ __forceinline__ void mma16816h(float* c, const uint32_t* a, uint32_t b0, uint32_t b1){
    asm volatile("mma.sync.aligned.m16n8k16.row.col.f32.f16.f16.f32 "
                 "{%0,%1,%2,%3}, {%4,%5,%6,%7}, {%8,%9}, {%0,%1,%2,%3};"
                 : "+f"(c[0]),"+f"(c[1]),"+f"(c[2]),"+f"(c[3])
                 : "r"(a[0]),"r"(a[1]),"r"(a[2]),"r"(a[3]), "r"(b0),"r"(b1));
}
__device__ __forceinline__ void mma8(float* c, const uint32_t* a, uint32_t b0, uint32_t b1){
    asm volatile("mma.sync.aligned.m16n8k32.row.col.f32.e4m3.e4m3.f32 "
                 "{%0,%1,%2,%3}, {%4,%5,%6,%7}, {%8,%9}, {%0,%1,%2,%3};"
                 : "+f"(c[0]),"+f"(c[1]),"+f"(c[2]),"+f"(c[3])
                 : "r"(a[0]),"r"(a[1]),"r"(a[2]),"r"(a[3]), "r"(b0),"r"(b1));
}
__device__ __forceinline__ void st2h(h16* D, float v0, float v1){
    __half2 p; p.x = __float2half_rn(v0); p.y = __float2half_rn(v1);
    *(__half2*)D = p;
}

// =================== conv: fp8 e4m3, CTA 128x256, warp 64x64, 4-stage ========
// row stride 48 bytes (32 data + 16 pad) -> every row 16B-aligned for ldmatrix,
// 8-row phase hits banks {0,12,24,4,16,28,8,20} (stride 12 words) = conflict-free
#define C8_ALD  48                  // A row stride (bytes)
#define C8_BLD  48                  // B row stride (bytes)
#define C8_BOFF 6144                // after A (128*48)
#define C8_STAGE 18432              // bytes per stage (A 6144 + B 12288)
#define C_NSTG  4
#define CONV_SMEM (C_NSTG*C8_STAGE) // 73728
#define NCHUNK  392                 // 49 taps * 8 chunks of 32 ch

__device__ __forceinline__ void conv_load_chunk(
    uint32_t smb, int stage,
    const uint8_t* __restrict__ x8, const uint8_t* __restrict__ w8t,
    long bV, int p0, int ic, int tid)
{
    int tap = ic >> 3, c0 = (ic & 7) * 32;
    int ky = tap / 7, kx = tap - ky*7;
    uint32_t base = smb + stage*C8_STAGE;

    // ---- A: 128 pos-rows x 32 fp8 ----
    int row  = tid >> 1;
    int half = tid & 1;
    int pos = p0 + row;
    int hs = (pos >> 6) + ky - 3, ws = (pos & 63) + kx - 3;
    int sz = (((unsigned)hs < 64u) && ((unsigned)ws < 64u)) ? 16 : 0;
    long sidx = sz ? (bV + ((hs << 6) + ws)) * CIN + c0 + half*16 : 0;
    cp16(base + (uint32_t)(row*C8_ALD + half*16), x8 + sidx, sz);

    // ---- B: 256 e-rows x 32 fp8 (transposed weights) ----
    #pragma unroll
    for (int q = 0; q < 2; q++){
        int qq = tid*2 + q;
        int brow = qq >> 1;
        int bh   = qq & 1;
        long widx = ((long)tap*En + brow)*CIN + c0 + bh*16;
        cp16(base + (uint32_t)(C8_BOFF + brow*C8_BLD + bh*16), w8t + widx, 16);
    }
    asm volatile("cp.async.commit_group;" ::: "memory");
}

__global__ void __launch_bounds__(256, 1)
conv_mma(const uint8_t* __restrict__ x8, const uint8_t* __restrict__ w8t,
         const float* __restrict__ bm, h16* __restrict__ M16)
{
    extern __shared__ char smem[];
    uint32_t smb = smem_u32(smem);
    int tid = threadIdx.x;
    int wid = tid >> 5, lane = tid & 31;
    int p0 = blockIdx.x * 128;
    int b  = blockIdx.y;
    long bV = (long)b * Vn;

    int mbase = (wid & 1) * 64;
    int nbase = (wid >> 1) * 64;

    float acc[4][8][4];
    #pragma unroll
    for (int i=0;i<4;i++)
    #pragma unroll
        for (int j=0;j<8;j++)
        #pragma unroll
            for (int k=0;k<4;k++) acc[i][j][k]=0.f;

    conv_load_chunk(smb, 0, x8, w8t, bV, p0, 0, tid);
    conv_load_chunk(smb, 1, x8, w8t, bV, p0, 1, tid);
    conv_load_chunk(smb, 2, x8, w8t, bV, p0, 2, tid);

    int stage = 0;
    for (int ic = 0; ic < NCHUNK; ic++){
        if (ic < NCHUNK-3) asm volatile("cp.async.wait_group 2;" ::: "memory");
        else               asm volatile("cp.async.wait_group 0;" ::: "memory");
        __syncthreads();
        if (ic + 3 < NCHUNK)
            conv_load_chunk(smb, (ic + 3) & 3, x8, w8t, bV, p0, ic + 3, tid);

        uint32_t sa = smb + (uint32_t)stage*C8_STAGE;
        uint32_t a8[4][4];
        #pragma unroll
        for (int mt = 0; mt < 4; mt++){
            uint32_t ad = sa + (uint32_t)((mbase + mt*16 + (lane & 15))*C8_ALD
                                          + (lane >> 4)*16);
            ldsm4(a8[mt], ad);
        }
        #pragma unroll
        for (int nb = 0; nb < 4; nb++){
            uint32_t rb[4];
            uint32_t bd = sa + (uint32_t)(C8_BOFF + (nbase + nb*16 + (lane & 15))*C8_BLD
                                          + (lane >> 4)*16);
            ldsm4(rb, bd);
            #pragma unroll
            for (int mt = 0; mt < 4; mt++){
                mma8(acc[mt][nb*2],   a8[mt], rb[0], rb[2]);   // n8 block even
                mma8(acc[mt][nb*2+1], a8[mt], rb[1], rb[3]);   // n8 block odd
            }
        }
        stage = (stage + 1) & 3;
    }

    // epilogue: unscale (w was x64), add bias, store fp16
    #pragma unroll
    for (int mt = 0; mt < 4; mt++){
        long r0 = bV + p0 + mbase + mt*16 + (lane >> 2);
        #pragma unroll
        for (int n8 = 0; n8 < 8; n8++){
            int col = nbase + n8*8 + (lane & 3)*2;
            float b0 = bm[col], b1 = bm[col+1];
            float* c = acc[mt][n8];
            st2h(M16 + r0*En + col,     c[0]*WSCALE_INV + b0, c[1]*WSCALE_INV + b1);
            st2h(M16 + (r0+8)*En + col, c[2]*WSCALE_INV + b0, c[3]*WSCALE_INV + b1);
        }
    }
}

// =================== NN fp16 GEMM (1-pass) ===================================
#define A_LD   40
#define B_LD   136
#define OFF_A  0
#define OFF_B  5120
#define STAGE_E 9472
#define GEMM_SMEM (2*STAGE_E*2)

__device__ __forceinline__ void nn_load_chunk(
    uint32_t smb, int stage,
    const h16* __restrict__ Ah, const h16* __restrict__ Bs,
    int m0, int n0, int k0, int K, int N, int tid)
{
    uint32_t base = smb + stage*STAGE_E*2;
    int row  = tid >> 1;
    int koff = (tid & 1) * 16;
    long sidx = (long)(m0+row)*K + k0 + koff;
    uint32_t da = base + (uint32_t)(OFF_A + row*A_LD + koff)*2;
    cp16(da,      Ah + sidx,     16);
    cp16(da + 16, Ah + sidx + 8, 16);
    #pragma unroll
    for (int q = 0; q < 2; q++){
        int qq = tid*2 + q;
        int brow = qq >> 4;
        int bcol = (qq & 15) * 8;
        long widx = (long)(k0+brow)*N + n0 + bcol;
        cp16(base + (uint32_t)(OFF_B + brow*B_LD + bcol)*2, Bs + widx, 16);
    }
    asm volatile("cp.async.commit_group;" ::: "memory");
}

__global__ void __launch_bounds__(256, 2)
hgemm_nn(const h16* __restrict__ Ah, const h16* __restrict__ Bs,
         float* __restrict__ Cf, h16* __restrict__ Ch,
         const float* __restrict__ aux,
         int N, int K, long sA, long sB, long sC, long sAux, int epi)
{
    extern __shared__ char smem[];
    uint32_t smb = smem_u32(smem);
    int tid = threadIdx.x;
    int wid = tid >> 5, lane = tid & 31;
    int n0 = blockIdx.x * 128;
    int m0 = blockIdx.y * 128;
    int b  = blockIdx.z;
    Ah += (long)b*sA;
    Bs += (long)b*sB;
    const float* auxp = aux ? aux + (long)b*sAux : (const float*)0;

    int mbase = (wid & 3) * 32;
    int nbase = (wid >> 2) * 64;

    float acc[2][8][4];
    #pragma unroll
    for (int i=0;i<2;i++)
    #pragma unroll
        for (int j=0;j<8;j++)
        #pragma unroll
            for (int k=0;k<4;k++) acc[i][j][k]=0.f;

    int nchunk = K >> 5;
    nn_load_chunk(smb, 0, Ah, Bs, m0, n0, 0,  K, N, tid);
    nn_load_chunk(smb, 1, Ah, Bs, m0, n0, 32, K, N, tid);

    for (int ic = 0; ic < nchunk; ic++){
        if (ic < nchunk-2) asm volatile("cp.async.wait_group 1;" ::: "memory");
        else               asm volatile("cp.async.wait_group 0;" ::: "memory");
        __syncthreads();
        uint32_t sa = smb + (uint32_t)(ic & 1)*STAGE_E*2;
        #pragma unroll
        for (int kk = 0; kk < 2; kk++){
            uint32_t ah[2][4];
            #pragma unroll
            for (int mt = 0; mt < 2; mt++){
                uint32_t ad = sa + (uint32_t)((mbase + mt*16 + (lane & 15))*A_LD
                                              + kk*16 + (lane >> 4)*8)*2;
                ldsm4(ah[mt], ad);
            }
            #pragma unroll
            for (int nf = 0; nf < 4; nf++){
                uint32_t bh[4];
                uint32_t bd = sa + (uint32_t)(OFF_B + (kk*16 + (lane & 15))*B_LD
                                              + nbase + nf*16 + (lane >> 4)*8)*2;
                ldsm4t(bh, bd);
                #pragma unroll
                for (int mt = 0; mt < 2; mt++){
                    mma16816h(acc[mt][nf*2],   ah[mt], bh[0], bh[1]);
                    mma16816h(acc[mt][nf*2+1], ah[mt], bh[2], bh[3]);
                }
            }
        }
        __syncthreads();
        if (ic + 2 < nchunk)
            nn_load_chunk(smb, ic & 1, Ah, Bs, m0, n0, (ic+2)*32, K, N, tid);
    }

    #pragma unroll
    for (int mt = 0; mt < 2; mt++){
        long r0 = m0 + mbase + mt*16 + (lane >> 2);
        #pragma unroll
        for (int n8 = 0; n8 < 8; n8++){
            int col = n0 + nbase + n8*8 + (lane & 3)*2;
            float* c = acc[mt][n8];
            float v00=c[0], v01=c[1], v10=c[2], v11=c[3];
            if (epi == 0){
                float b0 = auxp[col], b1 = auxp[col+1];
                v00+=b0; v01+=b1; v10+=b0; v11+=b1;
            } else if (epi == 1){
                v00=fabsf(v00); v01=fabsf(v01); v10=fabsf(v10); v11=fabsf(v11);
            } else {
                v00 = auxp[r0*N + col]     - v00;
                v01 = auxp[r0*N + col + 1] - v01;
                v10 = auxp[(r0+8)*N + col]     - v10;
                v11 = auxp[(r0+8)*N + col + 1] - v11;
            }
            if (Cf){
                float* base = Cf + (long)b*sC;
                *(float2*)(base + r0*N + col)     = make_float2(v00, v01);
                *(float2*)(base + (r0+8)*N + col) = make_float2(v10, v11);
            }
            if (Ch){
                h16* bh = Ch + (long)b*sC;
                st2h(bh + r0*N + col,     v00, v01);
                st2h(bh + (r0+8)*N + col, v10, v11);
            }
        }
    }
}

// =================== TN fp16 1-pass split-K partials =========================
#define TN_A    0
#define TN_B    4352
#define TN_STAGE 8704
#define TN_SMEM (2*TN_STAGE*2)

__device__ __forceinline__ void tn_load_chunk(
    uint32_t smb, int stage,
    const h16* __restrict__ Ah, const h16* __restrict__ Bs,
    long offA, long offB, int m0, int n0, int k0, int lda, int ldb, int tid)
{
    uint32_t base = smb + stage*TN_STAGE*2;
    #pragma unroll
    for (int q = 0; q < 2; q++){
        int qq = tid*2 + q;
        int brow = qq >> 4;
        int bcol = (qq & 15) * 8;
        long aidx = offA + (long)(k0+brow)*lda + m0 + bcol;
        cp16(base + (uint32_t)(TN_A + brow*B_LD + bcol)*2, Ah + aidx, 16);
        long bidx = offB + (long)(k0+brow)*ldb + n0 + bcol;
        cp16(base + (uint32_t)(TN_B + brow*B_LD + bcol)*2, Bs + bidx, 16);
    }
    asm volatile("cp.async.commit_group;" ::: "memory");
}

__global__ void __launch_bounds__(256, 2)
hgemm_tn(const h16* __restrict__ Ah, const h16* __restrict__ Bs,
         float* __restrict__ P, int Mo, int No, int lda, int ldb, int Kc,
         long sA, long sB)
{
    extern __shared__ char smem[];
    uint32_t smb = smem_u32(smem);
    int tid = threadIdx.x;
    int wid = tid >> 5, lane = tid & 31;
    int b = blockIdx.z / NCH, s = blockIdx.z % NCH;
    long offA = (long)b*sA + (long)s*Kc*lda;
    long offB = (long)b*sB + (long)s*Kc*ldb;
    P += (long)(b*NCH + s)*Mo*No;
    int n0 = blockIdx.x * 128;
    int m0 = blockIdx.y * 128;

    int mbase = (wid & 3) * 32;
    int nbase = (wid >> 2) * 64;

    float acc[2][8][4];
    #pragma unroll
    for (int i=0;i<2;i++)
    #pragma unroll
        for (int j=0;j<8;j++)
        #pragma unroll
            for (int k=0;k<4;k++) acc[i][j][k]=0.f;

    int nchunk = Kc >> 5;
    tn_load_chunk(smb, 0, Ah, Bs, offA, offB, m0, n0, 0,  lda, ldb, tid);
    tn_load_chunk(smb, 1, Ah, Bs, offA, offB, m0, n0, 32, lda, ldb, tid);

    int krow = (lane & 7) + (lane >> 4)*8;
    int msub = ((lane >> 3) & 1)*8;

    for (int ic = 0; ic < nchunk; ic++){
        if (ic < nchunk-2) asm volatile("cp.async.wait_group 1;" ::: "memory");
        else               asm volatile("cp.async.wait_group 0;" ::: "memory");
        __syncthreads();
        uint32_t sa = smb + (uint32_t)(ic & 1)*TN_STAGE*2;
        #pragma unroll
        for (int kk = 0; kk < 2; kk++){
            uint32_t ah[2][4];
            #pragma unroll
            for (int mt = 0; mt < 2; mt++){
                uint32_t ad = sa + (uint32_t)(TN_A + (kk*16 + krow)*B_LD
                                              + mbase + mt*16 + msub)*2;
                ldsm4t(ah[mt], ad);
            }
            #pragma unroll
            for (int nf = 0; nf < 4; nf++){
                uint32_t bh[4];
                uint32_t bd = sa + (uint32_t)(TN_B + (kk*16 + (lane & 15))*B_LD
                                              + nbase + nf*16 + (lane >> 4)*8)*2;
                ldsm4t(bh, bd);
                #pragma unroll
                for (int mt = 0; mt < 2; mt++){
                    mma16816h(acc[mt][nf*2],   ah[mt], bh[0], bh[1]);
                    mma16816h(acc[mt][nf*2+1], ah[mt], bh[2], bh[3]);
                }
            }
        }
        __syncthreads();
        if (ic + 2 < nchunk)
            tn_load_chunk(smb, ic & 1, Ah, Bs, offA, offB, m0, n0, (ic+2)*32, lda, ldb, tid);
    }

    #pragma unroll
    for (int mt = 0; mt < 2; mt++){
        long r0 = m0 + mbase + mt*16 + (lane >> 2);
        #pragma unroll
        for (int n8 = 0; n8 < 8; n8++){
            int col = n0 + nbase + n8*8 + (lane & 3)*2;
            float* c = acc[mt][n8];
            *(float2*)(P + r0*No + col)     = make_float2(c[0], c[1]);
            *(float2*)(P + (r0+8)*No + col) = make_float2(c[2], c[3]);
        }
    }
}

// ---------------- small kernels ---------------------------------------------
__global__ void xmean_part(const float* __restrict__ x, float* __restrict__ xp){
    int b=blockIdx.x, s=blockIdx.y, tid=threadIdx.x;
    const float* p = x + ((long)b*Vn + s*(Vn/NCH))*CIN + tid;
    float acc=0.f;
    for (int i=0;i<Vn/NCH;i++) acc += p[(long)i*CIN];
    xp[(b*NCH+s)*CIN+tid]=acc;
}

__global__ void a_kernel(const float* __restrict__ xp, const float* __restrict__ w_a,
                         const float* __restrict__ b_a, float* __restrict__ a){
    __shared__ float xm[CIN];
    __shared__ float part[256];
    int b=blockIdx.x, tid=threadIdx.x;
    float acc=0.f;
    #pragma unroll
    for (int ch=0;ch<NCH;ch++) acc += xp[(b*NCH+ch)*CIN+tid];
    xm[tid] = acc * (1.0f/(float)Vn);
    __syncthreads();
    int f = tid & 127, half = tid >> 7;
    float s = 0.f;
    #pragma unroll 4
    for (int c = half*128; c < half*128 + 128; c++) s += xm[c]*w_a[c*Fn+f];
    part[tid] = s;
    __syncthreads();
    if (tid < Fn) a[b*Fn+tid] = part[tid] + part[tid+128] + b_a[tid];
}

__global__ void colsum_part(const h16* __restrict__ Hm, float* __restrict__ cp){
    int b=blockIdx.x, s=blockIdx.y, tid=threadIdx.x;
    const h16* p = Hm + ((long)b*Vn + s*(Vn/NCH))*En + tid;
    float acc=0.f;
    for (int i=0;i<Vn/NCH;i++) acc += __half2float(p[(long)i*En]);
    cp[(b*NCH+s)*En+tid]=acc;
}

__global__ void binv_kernel(const float* __restrict__ cp, float* __restrict__ binv){
    int b=blockIdx.x, tid=threadIdx.x;
    float s=0.f;
    #pragma unroll
    for (int ch=0;ch<NCH;ch++) s += cp[(b*NCH+ch)*En+tid];
    binv[b*En+tid] = 1.0f/s;
}

__global__ void rowscale_h(h16* __restrict__ H16){
    __shared__ float red[256];
    long row = blockIdx.x;
    int tid = threadIdx.x;
    float v = __half2float(H16[row*En + tid]);
    red[tid]=v; __syncthreads();
    for (int s=128;s>0;s>>=1){ if(tid<s) red[tid]+=red[tid+s]; __syncthreads(); }
    H16[row*En + tid] = __float2half_rn(v * rsqrtf(red[0]));
}

__global__ void reduce_scale_h(h16* __restrict__ outv, const float* __restrict__ part,
                               const float* __restrict__ scale, int R, int C){
    long idx = (long)blockIdx.x*256 + threadIdx.x;
    int c = (int)(idx % C); long rc = idx / C; int r = (int)(rc % R); int b = (int)(rc / R);
    float s=0.f;
#pragma unroll
    for (int ch=0;ch<NCH;ch++) s += part[((long)(b*NCH+ch)*R + r)*C + c];
    outv[idx] = __float2half_rn(s * scale[b*R + r]);
}

// ---------------- host launch ------------------------------------------------
extern "C" void kernel_launch(void* const* d_in, const int* in_sizes, int n_in,
                              void* d_out, int out_size){
    (void)in_sizes; (void)n_in; (void)out_size;
    const float* x    =(const float*)d_in[0];
    const float* wphi =(const float*)d_in[1];
    const float* bphi =(const float*)d_in[2];
    const float* wa   =(const float*)d_in[3];
    const float* ba   =(const float*)d_in[4];
    const float* wm   =(const float*)d_in[5];
    const float* bm   =(const float*)d_in[6];
    const float* w2   =(const float*)d_in[7];
    const float* b2   =(const float*)d_in[8];
    float* out=(float*)d_out;

    float *aV,*binv,*p1,*p2,*xp,*cp;
    h16 *x16,*wphi16,*w216,*phi16,*M16,*H16,*t16,*tmp16,*y16;
    uint8_t *x8,*w8t;
    cudaGetSymbolAddress((void**)&aV  , g_a);
    cudaGetSymbolAddress((void**)&binv, g_Binv);
    cudaGetSymbolAddress((void**)&p1  , g_p1);
    cudaGetSymbolAddress((void**)&p2  , g_p2);
    cudaGetSymbolAddress((void**)&xp  , g_xp);
    cudaGetSymbolAddress((void**)&cp  , g_cp);
    cudaGetSymbolAddress((void**)&x16 , g_x16);
    cudaGetSymbolAddress((void**)&wphi16, g_wphi16);
    cudaGetSymbolAddress((void**)&w216, g_w216);
    cudaGetSymbolAddress((void**)&phi16, g_phi16);
    cudaGetSymbolAddress((void**)&M16 , g_M16);
    cudaGetSymbolAddress((void**)&H16 , g_H16);
    cudaGetSymbolAddress((void**)&t16 , g_t16);
    cudaGetSymbolAddress((void**)&tmp16, g_tmp16);
    cudaGetSymbolAddress((void**)&y16 , g_y16);
    cudaGetSymbolAddress((void**)&x8  , g_x8);
    cudaGetSymbolAddress((void**)&w8t , g_w8t);

    cudaFuncSetAttribute(conv_mma, cudaFuncAttributeMaxDynamicSharedMemorySize, CONV_SMEM);
    cudaFuncSetAttribute(hgemm_nn, cudaFuncAttributeMaxDynamicSharedMemorySize, GEMM_SMEM);
    cudaFuncSetAttribute(hgemm_tn, cudaFuncAttributeMaxDynamicSharedMemorySize, TN_SMEM);

    // converts: x -> fp16+fp8, wphi/w2 -> fp16; wm -> fp8 transposed
    cvt_all<<<(N_CV + 255)/256, 256>>>(x, wphi, w2, x16, x8, wphi16, w216);
    cvt_wt8<<<49*64, 256>>>(wm, w8t);

    // mean(x) -> a
    xmean_part<<<dim3(Bn,NCH),256>>>(x, xp);
    a_kernel<<<Bn,256>>>(xp, wa, ba, aV);

    // phi = x @ w_phi + b_phi -> fp16 (M=32768, N=128, K=256)
    hgemm_nn<<<dim3(1,256,1),256,GEMM_SMEM>>>(x16, wphi16,
        (float*)0, phi16, bphi, Fn, CIN, 0,0,(long)0,0, 0);

    // M = conv7x7(x) + b_m -> fp16  (fp8 e4m3 MMA)
    conv_mma<<<dim3(32, Bn), 256, CONV_SMEM>>>(x8, w8t, bm, M16);

    // t = a * (phi^T @ M) -> fp16
    hgemm_tn<<<dim3(2,1,Bn*NCH),256,TN_SMEM>>>(phi16, M16, p1,
        Fn, En, Fn, En, Vn/NCH, (long)Vn*Fn, (long)Vn*En);
    reduce_scale_h<<<(Bn*Fn*En)/256,256>>>(t16, p1, aV, Fn, En);

    // H = |phi @ t| -> fp16
    hgemm_nn<<<dim3(2,32,Bn),256,GEMM_SMEM>>>(phi16, t16,
        (float*)0, H16, (const float*)0, En, Fn,
        (long)Vn*Fn, (long)Fn*En, (long)Vn*En, 0, 1);

    // Binv from column sums of H
    colsum_part<<<dim3(Bn,NCH),256>>>(H16, cp);
    binv_kernel<<<Bn,256>>>(cp, binv);

    // D_H = D^{-1/2} H  (in-place fp16)
    rowscale_h<<<Bn*Vn,256>>>(H16);

    // tmp = Binv * (D_H^T @ x) -> fp16
    hgemm_tn<<<dim3(2,2,Bn*NCH),256,TN_SMEM>>>(H16, x16, p2,
        En, CIN, En, CIN, Vn/NCH, (long)Vn*En, (long)Vn*CIN);
    reduce_scale_h<<<(Bn*En*CIN)/256,256>>>(tmp16, p2, binv, En, CIN);

    // y = x - D_H @ tmp -> fp16
    hgemm_nn<<<dim3(2,32,Bn),256,GEMM_SMEM>>>(H16, tmp16,
        (float*)0, y16, x, CIN, En,
        (long)Vn*En, (long)En*CIN, (long)Vn*CIN, (long)Vn*CIN, 2);

    // out = y @ w2 + b2
    hgemm_nn<<<dim3(2,256,1),256,GEMM_SMEM>>>(y16, w216,
        out, (h16*)0, b2, En, CIN, 0,0,(long)0,0, 0);
}

// round 17
// speedup vs baseline: 1.2188x; 1.2188x over previous
#include <cuda_runtime.h>
#include <cuda_bf16.h>
#include <cuda_fp16.h>
#include <cstdint>

typedef __half h16;

#define Bn   8
#define Vn   4096
#define CIN  256
#define Fn   128
#define En   256
#define NCH  16

// ---------------- scratch (device globals) -----------------------------------
__device__ float g_a   [Bn*Fn];
__device__ float g_Binv[Bn*En];
__device__ float g_p1  [Bn*NCH*Fn*En];
__device__ float g_p2  [Bn*NCH*En*CIN];
__device__ float g_xp  [Bn*NCH*CIN];
__device__ float g_cp  [Bn*NCH*En];
// fp16 operands
__device__ h16 g_x16 [Bn*Vn*CIN];
__device__ h16 g_w16 [49*CIN*En];
__device__ h16 g_wphi16[CIN*Fn];
__device__ h16 g_w216[CIN*En];
__device__ h16 g_phi16[Bn*Vn*Fn];
__device__ h16 g_M16 [Bn*Vn*En];
__device__ h16 g_H16 [Bn*Vn*En];
__device__ h16 g_t16 [Bn*Fn*En];
__device__ h16 g_tmp16[Bn*En*CIN];
__device__ h16 g_y16 [Bn*Vn*CIN];

// =================== helpers =================================================
#define N_X  (Bn*Vn*CIN)
#define N_WM (49*CIN*En)
#define N_WP (CIN*Fn)
#define N_W2 (CIN*En)
#define N_ALL (N_X + N_WM + N_WP + N_W2)

__global__ void cvt_all(const float* __restrict__ x, const float* __restrict__ wm,
                        const float* __restrict__ wphi, const float* __restrict__ w2,
                        h16* __restrict__ x16, h16* __restrict__ w16,
                        h16* __restrict__ wphi16, h16* __restrict__ w216){
    long i = (long)blockIdx.x*256 + threadIdx.x;
    if (i < N_X)                      x16[i]            = __float2half_rn(x[i]);
    else if (i < N_X+N_WM)            w16[i-N_X]        = __float2half_rn(wm[i-N_X]);
    else if (i < N_X+N_WM+N_WP)       wphi16[i-N_X-N_WM]= __float2half_rn(wphi[i-N_X-N_WM]);
    else if (i < N_ALL)               w216[i-N_X-N_WM-N_WP] = __float2half_rn(w2[i-N_X-N_WM-N_WP]);
}

__device__ __forceinline__ uint32_t smem_u32(const void* p) {
    uint32_t a;
    asm("{ .reg .u64 t; cvta.to.shared.u64 t, %1; cvt.u32.u64 %0, t; }" : "=r"(a) : "l"(p));
    return a;
}
__device__ __forceinline__ void cp16(uint32_t d, const void* s, int sz){
    asm volatile("cp.async.cg.shared.global [%0], [%1], 16, %2;"
                 :: "r"(d), "l"(s), "r"(sz) : "memory");
}
__device__ __forceinline__ void ldsm4(uint32_t* r, uint32_t a){
    asm volatile("ldmatrix.sync.aligned.m8n8.x4.shared.b16 {%0,%1,%2,%3}, [%4];"
                 : "=r"(r[0]),"=r"(r[1]),"=r"(r[2]),"=r"(r[3]) : "r"(a));
}
__device__ __forceinline__ void ldsm4t(uint32_t* r, uint32_t a){
    asm volatile("ldmatrix.sync.aligned.m8n8.x4.trans.shared.b16 {%0,%1,%2,%3}, [%4];"
                 : "=r"(r[0]),"=r"(r[1]),"=r"(r[2]),"=r"(r[3]) : "r"(a));
}
__device__ __forceinline__ void mma16816h(float* c, const uint32_t* a, uint32_t b0, uint32_t b1){
    asm volatile("mma.sync.aligned.m16n8k16.row.col.f32.f16.f16.f32 "
                 "{%0,%1,%2,%3}, {%4,%5,%6,%7}, {%8,%9}, {%0,%1,%2,%3};"
                 : "+f"(c[0]),"+f"(c[1]),"+f"(c[2]),"+f"(c[3])
                 : "r"(a[0]),"r"(a[1]),"r"(a[2]),"r"(a[3]), "r"(b0),"r"(b1));
}
// fp16-accumulator MMA (conv only; error damped by the H-branch ~1e-3 gain)
__device__ __forceinline__ void mma16816hh(uint32_t* c, const uint32_t* a, uint32_t b0, uint32_t b1){
    asm volatile("mma.sync.aligned.m16n8k16.row.col.f16.f16.f16.f16 "
                 "{%0,%1}, {%2,%3,%4,%5}, {%6,%7}, {%0,%1};"
                 : "+r"(c[0]),"+r"(c[1])
                 : "r"(a[0]),"r"(a[1]),"r"(a[2]),"r"(a[3]), "r"(b0),"r"(b1));
}
__device__ __forceinline__ void st2h(h16* D, float v0, float v1){
    __half2 p; p.x = __float2half_rn(v0); p.y = __float2half_rn(v1);
    *(__half2*)D = p;
}

// =================== conv: fp16 1-pass, fp16 acc, 2 CTAs/SM ==================
#define A_LD    40
#define B_LD    136
#define CB_LD   264
#define C_AH    0
#define C_BH    5120
#define C_STAGE 13568
#define C_NSTG  4
#define CONV_SMEM (C_NSTG*C_STAGE*2)   // 108544 B; x2 CTAs = 217 KB < 227 KB
#define NCHUNK  392

__device__ __forceinline__ void conv_load_chunk(
    uint32_t smb, int stage,
    const h16* __restrict__ x16, const h16* __restrict__ wf,
    long bV, int p0, int ic, int tid)
{
    int tap = ic >> 3, c0 = (ic & 7) * 32;
    int ky = tap / 7, kx = tap - ky*7;
    uint32_t base = smb + stage*C_STAGE*2;

    int row  = tid >> 1;
    int koff = (tid & 1) * 16;
    int pos = p0 + row;
    int hs = (pos >> 6) + ky - 3, ws = (pos & 63) + kx - 3;
    int sz = (((unsigned)hs < 64u) && ((unsigned)ws < 64u)) ? 16 : 0;
    long sidx = sz ? (bV + ((hs << 6) + ws)) * CIN + c0 + koff : 0;
    uint32_t da = base + (uint32_t)(C_AH + row*A_LD + koff)*2;
    cp16(da,      x16 + sidx,     sz);
    cp16(da + 16, x16 + sidx + 8, sz);

    #pragma unroll
    for (int q = 0; q < 4; q++){
        int qq = tid + 256*q;
        int brow = qq >> 5;
        int bcol = (qq & 31) * 8;
        long widx = ((long)(tap*CIN + c0 + brow))*En + bcol;
        cp16(base + (uint32_t)(C_BH + brow*CB_LD + bcol)*2, wf + widx, 16);
    }
    asm volatile("cp.async.commit_group;" ::: "memory");
}

__global__ void __launch_bounds__(256, 2)
conv_mma(const h16* __restrict__ x16, const h16* __restrict__ wf,
         const float* __restrict__ bm, h16* __restrict__ M16)
{
    extern __shared__ char smem[];
    uint32_t smb = smem_u32(smem);
    int tid = threadIdx.x;
    int wid = tid >> 5, lane = tid & 31;
    int p0 = blockIdx.x * 128;
    int b  = blockIdx.y;
    long bV = (long)b * Vn;

    int mbase = (wid & 1) * 64;
    int nbase = (wid >> 1) * 64;

    uint32_t facc[4][8][2];
    #pragma unroll
    for (int i=0;i<4;i++)
    #pragma unroll
        for (int j=0;j<8;j++){ facc[i][j][0]=0u; facc[i][j][1]=0u; }

    conv_load_chunk(smb, 0, x16, wf, bV, p0, 0, tid);
    conv_load_chunk(smb, 1, x16, wf, bV, p0, 1, tid);
    conv_load_chunk(smb, 2, x16, wf, bV, p0, 2, tid);

    int stage = 0;
    for (int ic = 0; ic < NCHUNK; ic++){
        if (ic < NCHUNK-3) asm volatile("cp.async.wait_group 2;" ::: "memory");
        else               asm volatile("cp.async.wait_group 0;" ::: "memory");
        __syncthreads();
        if (ic + 3 < NCHUNK)
            conv_load_chunk(smb, (ic + 3) & 3, x16, wf, bV, p0, ic + 3, tid);

        uint32_t sa = smb + (uint32_t)stage*C_STAGE*2;
        #pragma unroll
        for (int kk = 0; kk < 2; kk++){
            uint32_t ah[4][4];
            #pragma unroll
            for (int mt = 0; mt < 4; mt++){
                uint32_t ad = sa + (uint32_t)((mbase + mt*16 + (lane & 15))*A_LD
                                              + kk*16 + (lane >> 4)*8)*2;
                ldsm4(ah[mt], ad);
            }
            #pragma unroll
            for (int nf = 0; nf < 4; nf++){
                uint32_t bh[4];
                uint32_t bd = sa + (uint32_t)(C_BH + (kk*16 + (lane & 15))*CB_LD
                                              + nbase + nf*16 + (lane >> 4)*8)*2;
                ldsm4t(bh, bd);
                #pragma unroll
                for (int mt = 0; mt < 4; mt++){
                    mma16816hh(facc[mt][nf*2],   ah[mt], bh[0], bh[1]);
                    mma16816hh(facc[mt][nf*2+1], ah[mt], bh[2], bh[3]);
                }
            }
        }
        stage = (stage + 1) & 3;
    }

    // epilogue: unpack fp16 acc, add bias (fp32), store fp16
    #pragma unroll
    for (int mt = 0; mt < 4; mt++){
        long r0 = bV + p0 + mbase + mt*16 + (lane >> 2);
        #pragma unroll
        for (int n8 = 0; n8 < 8; n8++){
            int col = nbase + n8*8 + (lane & 3)*2;
            float b0 = bm[col], b1 = bm[col+1];
            __half2 p0h = *(__half2*)&facc[mt][n8][0];
            __half2 p1h = *(__half2*)&facc[mt][n8][1];
            st2h(M16 + r0*En + col,     __half2float(p0h.x)+b0, __half2float(p0h.y)+b1);
            st2h(M16 + (r0+8)*En + col, __half2float(p1h.x)+b0, __half2float(p1h.y)+b1);
        }
    }
}

// =================== NN fp16 GEMM (1-pass) ===================================
#define OFF_A  0
#define OFF_B  5120
#define STAGE_E 9472
#define GEMM_SMEM (2*STAGE_E*2)

__device__ __forceinline__ void nn_load_chunk(
    uint32_t smb, int stage,
    const h16* __restrict__ Ah, const h16* __restrict__ Bs,
    int m0, int n0, int k0, int K, int N, int tid)
{
    uint32_t base = smb + stage*STAGE_E*2;
    int row  = tid >> 1;
    int koff = (tid & 1) * 16;
    long sidx = (long)(m0+row)*K + k0 + koff;
    uint32_t da = base + (uint32_t)(OFF_A + row*A_LD + koff)*2;
    cp16(da,      Ah + sidx,     16);
    cp16(da + 16, Ah + sidx + 8, 16);
    #pragma unroll
    for (int q = 0; q < 2; q++){
        int qq = tid*2 + q;
        int brow = qq >> 4;
        int bcol = (qq & 15) * 8;
        long widx = (long)(k0+brow)*N + n0 + bcol;
        cp16(base + (uint32_t)(OFF_B + brow*B_LD + bcol)*2, Bs + widx, 16);
    }
    asm volatile("cp.async.commit_group;" ::: "memory");
}

__global__ void __launch_bounds__(256, 2)
hgemm_nn(const h16* __restrict__ Ah, const h16* __restrict__ Bs,
         float* __restrict__ Cf, h16* __restrict__ Ch,
         const float* __restrict__ aux,
         int N, int K, long sA, long sB, long sC, long sAux, int epi)
{
    extern __shared__ char smem[];
    uint32_t smb = smem_u32(smem);
    int tid = threadIdx.x;
    int wid = tid >> 5, lane = tid & 31;
    int n0 = blockIdx.x * 128;
    int m0 = blockIdx.y * 128;
    int b  = blockIdx.z;
    Ah += (long)b*sA;
    Bs += (long)b*sB;
    const float* auxp = aux ? aux + (long)b*sAux : (const float*)0;

    int mbase = (wid & 3) * 32;
    int nbase = (wid >> 2) * 64;

    float acc[2][8][4];
    #pragma unroll
    for (int i=0;i<2;i++)
    #pragma unroll
        for (int j=0;j<8;j++)
        #pragma unroll
            for (int k=0;k<4;k++) acc[i][j][k]=0.f;

    int nchunk = K >> 5;
    nn_load_chunk(smb, 0, Ah, Bs, m0, n0, 0,  K, N, tid);
    nn_load_chunk(smb, 1, Ah, Bs, m0, n0, 32, K, N, tid);

    for (int ic = 0; ic < nchunk; ic++){
        if (ic < nchunk-2) asm volatile("cp.async.wait_group 1;" ::: "memory");
        else               asm volatile("cp.async.wait_group 0;" ::: "memory");
        __syncthreads();
        uint32_t sa = smb + (uint32_t)(ic & 1)*STAGE_E*2;
        #pragma unroll
        for (int kk = 0; kk < 2; kk++){
            uint32_t ah[2][4];
            #pragma unroll
            for (int mt = 0; mt < 2; mt++){
                uint32_t ad = sa + (uint32_t)((mbase + mt*16 + (lane & 15))*A_LD
                                              + kk*16 + (lane >> 4)*8)*2;
                ldsm4(ah[mt], ad);
            }
            #pragma unroll
            for (int nf = 0; nf < 4; nf++){
                uint32_t bh[4];
                uint32_t bd = sa + (uint32_t)(OFF_B + (kk*16 + (lane & 15))*B_LD
                                              + nbase + nf*16 + (lane >> 4)*8)*2;
                ldsm4t(bh, bd);
                #pragma unroll
                for (int mt = 0; mt < 2; mt++){
                    mma16816h(acc[mt][nf*2],   ah[mt], bh[0], bh[1]);
                    mma16816h(acc[mt][nf*2+1], ah[mt], bh[2], bh[3]);
                }
            }
        }
        __syncthreads();
        if (ic + 2 < nchunk)
            nn_load_chunk(smb, ic & 1, Ah, Bs, m0, n0, (ic+2)*32, K, N, tid);
    }

    #pragma unroll
    for (int mt = 0; mt < 2; mt++){
        long r0 = m0 + mbase + mt*16 + (lane >> 2);
        #pragma unroll
        for (int n8 = 0; n8 < 8; n8++){
            int col = n0 + nbase + n8*8 + (lane & 3)*2;
            float* c = acc[mt][n8];
            float v00=c[0], v01=c[1], v10=c[2], v11=c[3];
            if (epi == 0){
                float b0 = auxp[col], b1 = auxp[col+1];
                v00+=b0; v01+=b1; v10+=b0; v11+=b1;
            } else if (epi == 1){
                v00=fabsf(v00); v01=fabsf(v01); v10=fabsf(v10); v11=fabsf(v11);
            } else {
                v00 = auxp[r0*N + col]     - v00;
                v01 = auxp[r0*N + col + 1] - v01;
                v10 = auxp[(r0+8)*N + col]     - v10;
                v11 = auxp[(r0+8)*N + col + 1] - v11;
            }
            if (Cf){
                float* base = Cf + (long)b*sC;
                *(float2*)(base + r0*N + col)     = make_float2(v00, v01);
                *(float2*)(base + (r0+8)*N + col) = make_float2(v10, v11);
            }
            if (Ch){
                h16* bh = Ch + (long)b*sC;
                st2h(bh + r0*N + col,     v00, v01);
                st2h(bh + (r0+8)*N + col, v10, v11);
            }
        }
    }
}

// =================== TN fp16 1-pass split-K partials =========================
#define TN_A    0
#define TN_B    4352
#define TN_STAGE 8704
#define TN_SMEM (2*TN_STAGE*2)

__device__ __forceinline__ void tn_load_chunk(
    uint32_t smb, int stage,
    const h16* __restrict__ Ah, const h16* __restrict__ Bs,
    long offA, long offB, int m0, int n0, int k0, int lda, int ldb, int tid)
{
    uint32_t base = smb + stage*TN_STAGE*2;
    #pragma unroll
    for (int q = 0; q < 2; q++){
        int qq = tid*2 + q;
        int brow = qq >> 4;
        int bcol = (qq & 15) * 8;
        long aidx = offA + (long)(k0+brow)*lda + m0 + bcol;
        cp16(base + (uint32_t)(TN_A + brow*B_LD + bcol)*2, Ah + aidx, 16);
        long bidx = offB + (long)(k0+brow)*ldb + n0 + bcol;
        cp16(base + (uint32_t)(TN_B + brow*B_LD + bcol)*2, Bs + bidx, 16);
    }
    asm volatile("cp.async.commit_group;" ::: "memory");
}

__global__ void __launch_bounds__(256, 2)
hgemm_tn(const h16* __restrict__ Ah, const h16* __restrict__ Bs,
         float* __restrict__ P, int Mo, int No, int lda, int ldb, int Kc,
         long sA, long sB)
{
    extern __shared__ char smem[];
    uint32_t smb = smem_u32(smem);
    int tid = threadIdx.x;
    int wid = tid >> 5, lane = tid & 31;
    int b = blockIdx.z / NCH, s = blockIdx.z % NCH;
    long offA = (long)b*sA + (long)s*Kc*lda;
    long offB = (long)b*sB + (long)s*Kc*ldb;
    P += (long)(b*NCH + s)*Mo*No;
    int n0 = blockIdx.x * 128;
    int m0 = blockIdx.y * 128;

    int mbase = (wid & 3) * 32;
    int nbase = (wid >> 2) * 64;

    float acc[2][8][4];
    #pragma unroll
    for (int i=0;i<2;i++)
    #pragma unroll
        for (int j=0;j<8;j++)
        #pragma unroll
            for (int k=0;k<4;k++) acc[i][j][k]=0.f;

    int nchunk = Kc >> 5;
    tn_load_chunk(smb, 0, Ah, Bs, offA, offB, m0, n0, 0,  lda, ldb, tid);
    tn_load_chunk(smb, 1, Ah, Bs, offA, offB, m0, n0, 32, lda, ldb, tid);

    int krow = (lane & 7) + (lane >> 4)*8;
    int msub = ((lane >> 3) & 1)*8;

    for (int ic = 0; ic < nchunk; ic++){
        if (ic < nchunk-2) asm volatile("cp.async.wait_group 1;" ::: "memory");
        else               asm volatile("cp.async.wait_group 0;" ::: "memory");
        __syncthreads();
        uint32_t sa = smb + (uint32_t)(ic & 1)*TN_STAGE*2;
        #pragma unroll
        for (int kk = 0; kk < 2; kk++){
            uint32_t ah[2][4];
            #pragma unroll
            for (int mt = 0; mt < 2; mt++){
                uint32_t ad = sa + (uint32_t)(TN_A + (kk*16 + krow)*B_LD
                                              + mbase + mt*16 + msub)*2;
                ldsm4t(ah[mt], ad);
            }
            #pragma unroll
            for (int nf = 0; nf < 4; nf++){
                uint32_t bh[4];
                uint32_t bd = sa + (uint32_t)(TN_B + (kk*16 + (lane & 15))*B_LD
                                              + nbase + nf*16 + (lane >> 4)*8)*2;
                ldsm4t(bh, bd);
                #pragma unroll
                for (int mt = 0; mt < 2; mt++){
                    mma16816h(acc[mt][nf*2],   ah[mt], bh[0], bh[1]);
                    mma16816h(acc[mt][nf*2+1], ah[mt], bh[2], bh[3]);
                }
            }
        }
        __syncthreads();
        if (ic + 2 < nchunk)
            tn_load_chunk(smb, ic & 1, Ah, Bs, offA, offB, m0, n0, (ic+2)*32, lda, ldb, tid);
    }

    #pragma unroll
    for (int mt = 0; mt < 2; mt++){
        long r0 = m0 + mbase + mt*16 + (lane >> 2);
        #pragma unroll
        for (int n8 = 0; n8 < 8; n8++){
            int col = n0 + nbase + n8*8 + (lane & 3)*2;
            float* c = acc[mt][n8];
            *(float2*)(P + r0*No + col)     = make_float2(c[0], c[1]);
            *(float2*)(P + (r0+8)*No + col) = make_float2(c[2], c[3]);
        }
    }
}

// ---------------- small kernels ---------------------------------------------
__global__ void xmean_part(const float* __restrict__ x, float* __restrict__ xp){
    int b=blockIdx.x, s=blockIdx.y, tid=threadIdx.x;
    const float* p = x + ((long)b*Vn + s*(Vn/NCH))*CIN + tid;
    float acc=0.f;
    for (int i=0;i<Vn/NCH;i++) acc += p[(long)i*CIN];
    xp[(b*NCH+s)*CIN+tid]=acc;
}

// grid (Bn, 8): each block computes 16 outputs of a[b, :]
__global__ void a_kernel(const float* __restrict__ xp, const float* __restrict__ w_a,
                         const float* __restrict__ b_a, float* __restrict__ a){
    __shared__ float xm[CIN];
    __shared__ float part[256];
    int b = blockIdx.x, fb = blockIdx.y;
    int tid = threadIdx.x;
    float acc = 0.f;
    #pragma unroll
    for (int ch = 0; ch < NCH; ch++) acc += xp[(b*NCH+ch)*CIN + tid];
    xm[tid] = acc * (1.0f/(float)Vn);
    __syncthreads();
    int fl = tid >> 4, cpart = tid & 15;
    int f = fb*16 + fl;
    float s = 0.f;
    #pragma unroll
    for (int c = cpart*16; c < cpart*16 + 16; c++) s += xm[c]*w_a[c*Fn+f];
    part[fl*16 + cpart] = s;
    __syncthreads();
    if (tid < 16){
        float t = b_a[fb*16 + tid];
        #pragma unroll
        for (int j = 0; j < 16; j++) t += part[tid*16 + j];
        a[b*Fn + fb*16 + tid] = t;
    }
}

__global__ void colsum_part(const h16* __restrict__ Hm, float* __restrict__ cp){
    int b=blockIdx.x, s=blockIdx.y, tid=threadIdx.x;
    const h16* p = Hm + ((long)b*Vn + s*(Vn/NCH))*En + tid;
    float acc=0.f;
    for (int i=0;i<Vn/NCH;i++) acc += __half2float(p[(long)i*En]);
    cp[(b*NCH+s)*En+tid]=acc;
}

__global__ void binv_kernel(const float* __restrict__ cp, float* __restrict__ binv){
    int b=blockIdx.x, tid=threadIdx.x;
    float s=0.f;
    #pragma unroll
    for (int ch=0;ch<NCH;ch++) s += cp[(b*NCH+ch)*En+tid];
    binv[b*En+tid] = 1.0f/s;
}

// in-place row-normalize H (fp16) — shuffle reduction, 1 barrier
__global__ void rowscale_h(h16* __restrict__ H16){
    __shared__ float red[8];
    long row = blockIdx.x;
    int tid = threadIdx.x, lane = tid & 31, wid = tid >> 5;
    float v = __half2float(H16[row*En + tid]);
    float s = v;
    #pragma unroll
    for (int off = 16; off > 0; off >>= 1)
        s += __shfl_xor_sync(0xFFFFFFFFu, s, off);
    if (lane == 0) red[wid] = s;
    __syncthreads();
    float tot = red[0]+red[1]+red[2]+red[3]+red[4]+red[5]+red[6]+red[7];
    H16[row*En + tid] = __float2half_rn(v * rsqrtf(tot));
}

__global__ void reduce_scale_h(h16* __restrict__ outv, const float* __restrict__ part,
                               const float* __restrict__ scale, int R, int C){
    long idx = (long)blockIdx.x*256 + threadIdx.x;
    int c = (int)(idx % C); long rc = idx / C; int r = (int)(rc % R); int b = (int)(rc / R);
    float s=0.f;
#pragma unroll
    for (int ch=0;ch<NCH;ch++) s += part[((long)(b*NCH+ch)*R + r)*C + c];
    outv[idx] = __float2half_rn(s * scale[b*R + r]);
}

// ---------------- host launch ------------------------------------------------
extern "C" void kernel_launch(void* const* d_in, const int* in_sizes, int n_in,
                              void* d_out, int out_size){
    (void)in_sizes; (void)n_in; (void)out_size;
    const float* x    =(const float*)d_in[0];
    const float* wphi =(const float*)d_in[1];
    const float* bphi =(const float*)d_in[2];
    const float* wa   =(const float*)d_in[3];
    const float* ba   =(const float*)d_in[4];
    const float* wm   =(const float*)d_in[5];
    const float* bm   =(const float*)d_in[6];
    const float* w2   =(const float*)d_in[7];
    const float* b2   =(const float*)d_in[8];
    float* out=(float*)d_out;

    float *aV,*binv,*p1,*p2,*xp,*cp;
    h16 *x16,*w16,*wphi16,*w216,*phi16,*M16,*H16,*t16,*tmp16,*y16;
    cudaGetSymbolAddress((void**)&aV  , g_a);
    cudaGetSymbolAddress((void**)&binv, g_Binv);
    cudaGetSymbolAddress((void**)&p1  , g_p1);
    cudaGetSymbolAddress((void**)&p2  , g_p2);
    cudaGetSymbolAddress((void**)&xp  , g_xp);
    cudaGetSymbolAddress((void**)&cp  , g_cp);
    cudaGetSymbolAddress((void**)&x16 , g_x16);
    cudaGetSymbolAddress((void**)&w16 , g_w16);
    cudaGetSymbolAddress((void**)&wphi16, g_wphi16);
    cudaGetSymbolAddress((void**)&w216, g_w216);
    cudaGetSymbolAddress((void**)&phi16, g_phi16);
    cudaGetSymbolAddress((void**)&M16 , g_M16);
    cudaGetSymbolAddress((void**)&H16 , g_H16);
    cudaGetSymbolAddress((void**)&t16 , g_t16);
    cudaGetSymbolAddress((void**)&tmp16, g_tmp16);
    cudaGetSymbolAddress((void**)&y16 , g_y16);

    cudaFuncSetAttribute(conv_mma, cudaFuncAttributeMaxDynamicSharedMemorySize, CONV_SMEM);
    cudaFuncSetAttribute(hgemm_nn, cudaFuncAttributeMaxDynamicSharedMemorySize, GEMM_SMEM);
    cudaFuncSetAttribute(hgemm_tn, cudaFuncAttributeMaxDynamicSharedMemorySize, TN_SMEM);

    // fp16 converts of all inputs (single launch)
    cvt_all<<<(N_ALL + 255)/256, 256>>>(x, wm, wphi, w2, x16, w16, wphi16, w216);

    // mean(x) -> a
    xmean_part<<<dim3(Bn,NCH),256>>>(x, xp);
    a_kernel<<<dim3(Bn,8),256>>>(xp, wa, ba, aV);

    // phi = x @ w_phi + b_phi -> fp16 (M=32768, N=128, K=256)
    hgemm_nn<<<dim3(1,256,1),256,GEMM_SMEM>>>(x16, wphi16,
        (float*)0, phi16, bphi, Fn, CIN, 0,0,(long)0,0, 0);

    // M = conv7x7(x) + b_m -> fp16 (fp16 acc, 2 CTAs/SM)
    conv_mma<<<dim3(32, Bn), 256, CONV_SMEM>>>(x16, w16, bm, M16);

    // t = a * (phi^T @ M) -> fp16
    hgemm_tn<<<dim3(2,1,Bn*NCH),256,TN_SMEM>>>(phi16, M16, p1,
        Fn, En, Fn, En, Vn/NCH, (long)Vn*Fn, (long)Vn*En);
    reduce_scale_h<<<(Bn*Fn*En)/256,256>>>(t16, p1, aV, Fn, En);

    // H = |phi @ t| -> fp16
    hgemm_nn<<<dim3(2,32,Bn),256,GEMM_SMEM>>>(phi16, t16,
        (float*)0, H16, (const float*)0, En, Fn,
        (long)Vn*Fn, (long)Fn*En, (long)Vn*En, 0, 1);

    // Binv from column sums of H
    colsum_part<<<dim3(Bn,NCH),256>>>(H16, cp);
    binv_kernel<<<Bn,256>>>(cp, binv);

    // D_H = D^{-1/2} H  (in-place fp16)
    rowscale_h<<<Bn*Vn,256>>>(H16);

    // tmp = Binv * (D_H^T @ x) -> fp16
    hgemm_tn<<<dim3(2,2,Bn*NCH),256,TN_SMEM>>>(H16, x16, p2,
        En, CIN, En, CIN, Vn/NCH, (long)Vn*En, (long)Vn*CIN);
    reduce_scale_h<<<(Bn*En*CIN)/256,256>>>(tmp16, p2, binv, En, CIN);

    // y = x - D_H @ tmp -> fp16
    hgemm_nn<<<dim3(2,32,Bn),256,GEMM_SMEM>>>(H16, tmp16,
        (float*)0, y16, x, CIN, En,
        (long)Vn*En, (long)En*CIN, (long)Vn*CIN, (long)Vn*CIN, 2);

    // out = y @ w2 + b2
    hgemm_nn<<<dim3(2,256,1),256,GEMM_SMEM>>>(y16, w216,
        out, (h16*)0, b2, En, CIN, 0,0,(long)0,0, 0);
}